// round 15
// baseline (speedup 1.0000x reference)
#include <cuda_runtime.h>
#include <cuda_bf16.h>
#include <cstdint>

#define EPS 1e-16f
#define W 1024
#define H 1024
#define ROWS 4          // output rows per thread/block
#define TPB 256         // 256 threads * 4 px = 1024 = full row width

// ---- packed f32x2 helpers (sm_103a) ----
__device__ __forceinline__ unsigned long long pk2(float lo, float hi) {
    unsigned long long r;
    asm("mov.b64 %0, {%1, %2};" : "=l"(r) : "f"(lo), "f"(hi));
    return r;
}
#define UNPK2(v, a, b) asm("mov.b64 {%0, %1}, %2;" : "=f"(a), "=f"(b) : "l"(v))
__device__ __forceinline__ unsigned long long f2add(unsigned long long a, unsigned long long b) {
    unsigned long long r;
    asm("add.rn.f32x2 %0, %1, %2;" : "=l"(r) : "l"(a), "l"(b));
    return r;
}
__device__ __forceinline__ unsigned long long f2mul(unsigned long long a, unsigned long long b) {
    unsigned long long r;
    asm("mul.rn.f32x2 %0, %1, %2;" : "=l"(r) : "l"(a), "l"(b));
    return r;
}
__device__ __forceinline__ unsigned long long f2fma(unsigned long long a, unsigned long long b,
                                                    unsigned long long c) {
    unsigned long long r;
    asm("fma.rn.f32x2 %0, %1, %2, %3;" : "=l"(r) : "l"(a), "l"(b), "l"(c));
    return r;
}

// out(x,y) = (dxf+dyf)*invF - dxf(x-1,y)*invF(x-1,y) - dyf(x,y-1)*invF(x,y-1)
// (G(x,y)=F(x-1,y), H(x,y)=F(x,y-1) on the reflect-padded grid).
// Rows in registers; 4B-stride smem edge exchange; packed f32x2 math.
__global__ __launch_bounds__(TPB, 6)
void curvature_kernel(const float* __restrict__ u, float* __restrict__ out) {
    const int tile = blockIdx.x;            // b * (H/ROWS) + row-tile
    const int b    = tile >> 8;             // H/ROWS = 256 tiles per image
    const int x0   = (tile & 255) * ROWS;   // first output row
    const int t    = threadIdx.x;
    const int y    = t * 4;                 // first output col (float4 granule)

    const float* ub = u   + (size_t)b * (H * W);
    float*       ob = out + (size_t)b * (H * W);

    // index-shifted edge arrays -> branchless reads in the main loop
    // edgeL[k][t]   read as left halo of thread t   (written by t-1 at [t])
    // edgeR[k][t+1] read as right halo of thread t  (written by t+1 at [t+1])
    __shared__ float edgeL[ROWS + 2][TPB + 1];
    __shared__ float edgeR[ROWS + 1][TPB + 1];

    // ---- 6 row-vectors (padded rows x0-1 .. x0+4), reflect-clamped in x ----
    float rows[ROWS + 2][4];
    #pragma unroll
    for (int m = 0; m < ROWS + 2; ++m) {
        int r = x0 - 1 + m;
        r = (r < 0) ? 1 : ((r >= H) ? (H - 2) : r);
        float4 v = *reinterpret_cast<const float4*>(ub + (size_t)r * W + y);
        rows[m][0] = v.x; rows[m][1] = v.y; rows[m][2] = v.z; rows[m][3] = v.w;
    }

    // ---- publish edges (fire-and-forget STS), boundary threads add reflect ----
    #pragma unroll
    for (int k = 0; k < ROWS + 2; ++k) edgeL[k][t + 1] = rows[k][3];
    #pragma unroll
    for (int k = 0; k < ROWS + 1; ++k) edgeR[k][t] = rows[k][0];
    if (t == 0) {
        #pragma unroll
        for (int k = 0; k < ROWS + 2; ++k) edgeL[k][0] = rows[k][1];      // col -1 -> 1
    }
    if (t == TPB - 1) {
        #pragma unroll
        for (int k = 0; k < ROWS + 1; ++k) edgeR[k][TPB] = rows[k][2];    // col W -> W-2
    }
    __syncthreads();

    const unsigned long long NEG1 = pk2(-1.0f, -1.0f);
    const unsigned long long EPS2 = pk2(EPS, EPS);

    float l0 = edgeL[0][t];
    unsigned long long Ap01 = 0ull, Ap23 = 0ull;   // A = dxf*invF, previous F-row

    #pragma unroll
    for (int k = 0; k <= ROWS; ++k) {
        const float l1 = edgeL[k + 1][t];
        const float r0 = edgeR[k][t + 1];

        // ---- scalar m-column (col y-1) F-term ----
        const float dxm = l1 - l0, dym = rows[k][0] - l0;
        const float iFm = rsqrtf(fmaf(dxm, dxm, fmaf(dym, dym, EPS)));
        const float Bm  = dym * iFm;

        // ---- packed cols y .. y+3 ----
        const unsigned long long q0_01 = pk2(rows[k][0], rows[k][1]);
        const unsigned long long q0_12 = pk2(rows[k][1], rows[k][2]);
        const unsigned long long q0_23 = pk2(rows[k][2], rows[k][3]);
        const unsigned long long q0_3r = pk2(rows[k][3], r0);
        const unsigned long long q1_01 = pk2(rows[k + 1][0], rows[k + 1][1]);
        const unsigned long long q1_23 = pk2(rows[k + 1][2], rows[k + 1][3]);

        const unsigned long long dx01 = f2fma(q0_01, NEG1, q1_01);  // q1 - q0
        const unsigned long long dx23 = f2fma(q0_23, NEG1, q1_23);
        const unsigned long long dy01 = f2fma(q0_01, NEG1, q0_12);  // shift - q0
        const unsigned long long dy23 = f2fma(q0_23, NEG1, q0_3r);

        const unsigned long long n01 = f2fma(dx01, dx01, f2fma(dy01, dy01, EPS2));
        const unsigned long long n23 = f2fma(dx23, dx23, f2fma(dy23, dy23, EPS2));
        float n0, n1, n2, n3;
        UNPK2(n01, n0, n1);
        UNPK2(n23, n2, n3);
        const float iF0 = rsqrtf(n0), iF1 = rsqrtf(n1);
        const float iF2 = rsqrtf(n2), iF3 = rsqrtf(n3);
        const unsigned long long iF01 = pk2(iF0, iF1);
        const unsigned long long iF23 = pk2(iF2, iF3);

        const unsigned long long s01 = f2add(dx01, dy01);
        const unsigned long long s23 = f2add(dx23, dy23);
        const unsigned long long P01 = f2mul(dy01, iF01);   // dy*iF (B-products)
        const unsigned long long P23 = f2mul(dy23, iF23);

        if (k > 0) {
            float P0, P1, P2, P3;
            UNPK2(P01, P0, P1);
            UNPK2(P23, P2, P3);
            const unsigned long long Bo01 = pk2(Bm, P0);
            const unsigned long long Bo23 = pk2(P1, P2);
            // o = (S*iF - Ap) - B   (same association as scalar version)
            const unsigned long long o01 =
                f2fma(Bo01, NEG1, f2fma(Ap01, NEG1, f2mul(s01, iF01)));
            const unsigned long long o23 =
                f2fma(Bo23, NEG1, f2fma(Ap23, NEG1, f2mul(s23, iF23)));
            float4 o;
            UNPK2(o01, o.x, o.y);
            UNPK2(o23, o.z, o.w);
            *reinterpret_cast<float4*>(ob + (size_t)(x0 + k - 1) * W + y) = o;
        }
        Ap01 = f2mul(dx01, iF01);
        Ap23 = f2mul(dx23, iF23);
        l0 = l1;
    }
}

extern "C" void kernel_launch(void* const* d_in, const int* in_sizes, int n_in,
                              void* d_out, int out_size) {
    const float* u = (const float*)d_in[0];
    float* out = (float*)d_out;
    const int batch = in_sizes[0] / (H * W);   // 16
    const int blocks = batch * (H / ROWS);     // 4096
    curvature_kernel<<<blocks, TPB>>>(u, out);
}